// round 7
// baseline (speedup 1.0000x reference)
#include <cuda_runtime.h>
#include <cuda_pipeline.h>

#define FULLMASK 0xffffffffu

constexpr int Nn = 8;
constexpr int Cc = 128;
constexpr int Hh = 160;
constexpr int Ww = 160;
constexpr int WC  = Ww * Cc;             // 20480
constexpr int HWC = Hh * WC;
constexpr int TOT = Nn * HWC;
constexpr int MARGIN = 20608;            // > one H-row stride, guards t=160 touches

// Margin-padded scratch: scans may read (and pass2/3 prefetch) one element
// past the end; reads land in margin or neighbor data (harmless), the one
// OOB store is guarded.
__device__ float g_mem[MARGIN + TOT + MARGIN];
#define G_BUF (g_mem + MARGIN)

__device__ __forceinline__ float4 ld4(const float* p) { return *(const float4*)p; }

__device__ __forceinline__ float4 relu4(float a, float b, float c, float d) {
    return make_float4(fmaxf(a, 0.f), fmaxf(b, 0.f), fmaxf(c, 0.f), fmaxf(d, 0.f));
}

// One scan step: carry d0..d3 (pre-relu state, 4 consecutive channels/lane),
// 9-tap conv along C via lane shuffles, zero-padded at C edges.
// d_new = relu(conv(d) + b) + x.
__device__ __forceinline__ void scan_step(float& d0, float& d1, float& d2, float& d3,
                                          float x0, float x1, float x2, float x3,
                                          const float wk[9], float b, int lane)
{
    float v[12];
    v[4] = d0; v[5] = d1; v[6] = d2; v[7] = d3;
    v[0]  = __shfl_up_sync(FULLMASK, d0, 1);
    v[1]  = __shfl_up_sync(FULLMASK, d1, 1);
    v[2]  = __shfl_up_sync(FULLMASK, d2, 1);
    v[3]  = __shfl_up_sync(FULLMASK, d3, 1);
    v[8]  = __shfl_down_sync(FULLMASK, d0, 1);
    v[9]  = __shfl_down_sync(FULLMASK, d1, 1);
    v[10] = __shfl_down_sync(FULLMASK, d2, 1);
    v[11] = __shfl_down_sync(FULLMASK, d3, 1);
    if (lane == 0)  { v[0] = 0.f; v[1] = 0.f; v[2]  = 0.f; v[3]  = 0.f; }
    if (lane == 31) { v[8] = 0.f; v[9] = 0.f; v[10] = 0.f; v[11] = 0.f; }
    float a0 = b, a1 = b, a2 = b, a3 = b;
    float e0 = 0.f, e1 = 0.f, e2 = 0.f, e3 = 0.f;
#pragma unroll
    for (int k = 0; k < 5; k++) {
        a0 = fmaf(wk[k], v[k + 0], a0);
        a1 = fmaf(wk[k], v[k + 1], a1);
        a2 = fmaf(wk[k], v[k + 2], a2);
        a3 = fmaf(wk[k], v[k + 3], a3);
    }
#pragma unroll
    for (int k = 5; k < 9; k++) {
        e0 = fmaf(wk[k], v[k + 0], e0);
        e1 = fmaf(wk[k], v[k + 1], e1);
        e2 = fmaf(wk[k], v[k + 2], e2);
        e3 = fmaf(wk[k], v[k + 3], e3);
    }
    d0 = fmaxf(a0 + e0, 0.f) + x0;
    d1 = fmaxf(a1 + e1, 0.f) + x1;
    d2 = fmaxf(a2 + e2, 0.f) + x2;
    d3 = fmaxf(a3 + e3, 0.f) + x3;
}

// In-place NHWC column scan. Compile-time STRIDE; cp.async ring of 16 slots
// managed as 4 groups of 4 (one commit + one wait per 4 steps); 16 steps
// unrolled per outer iter so all addresses are base+immediate.
// Processes t = 1..160 where t=160 is a dummy (store suppressed).
template<int STRIDE>
__device__ __forceinline__ void scan_col_g4(float* __restrict__ p,
                                            float* __restrict__ ring,
                                            const float wk[9], float b, int lane)
{
    float* my = ring + lane * 4;             // slot j at my + j*128
    float4 v0 = ld4(p);
    float d0 = v0.x, d1 = v0.y, d2 = v0.z, d3 = v0.w;
    *(float4*)p = relu4(d0, d1, d2, d3);

#pragma unroll
    for (int g = 0; g < 4; g++) {            // prime elements 1..16
#pragma unroll
        for (int i = 0; i < 4; i++)
            __pipeline_memcpy_async(my + (g * 4 + i) * 128,
                                    p + (1 + g * 4 + i) * STRIDE, 16);
        __pipeline_commit();
    }

    float*       wp = p + STRIDE;            // element (1+16*ob+j) at wp + j*STRIDE
    const float* rs = p + 17 * STRIDE;       // prefetch element (17+16*ob+j)
    for (int ob = 0; ob < 10; ob++) {
#pragma unroll
        for (int grp = 0; grp < 4; grp++) {
            __pipeline_wait_prior(3);
#pragma unroll
            for (int i = 0; i < 4; i++) {
                const int j = grp * 4 + i;
                float4 cx = *(float4*)(my + j * 128);
                scan_step(d0, d1, d2, d3, cx.x, cx.y, cx.z, cx.w, wk, b, lane);
                if (j != 15) {
                    *(float4*)(wp + j * STRIDE) = relu4(d0, d1, d2, d3);
                } else if (ob != 9) {        // t=160 is dummy: no store
                    *(float4*)(wp + j * STRIDE) = relu4(d0, d1, d2, d3);
                }
            }
            if (ob != 9) {
#pragma unroll
                for (int i = 0; i < 4; i++) {
                    const int j = grp * 4 + i;
                    __pipeline_memcpy_async(my + j * 128, rs + j * STRIDE, 16);
                }
            }
            __pipeline_commit();             // uniform group count
        }
        wp += 16 * STRIDE; rs += 16 * STRIDE;
    }
}

// Pass 1 (down, H ascending): x NCHW -> G_BUF NHWC. cp.async staged transpose;
// ring of 20 slots = 5 groups of 4; one wait + one __syncthreads + one commit
// per 4 elements; 20 elements unrolled per outer iter.
__global__ void __launch_bounds__(128) k_pass1(const float* __restrict__ x,
                                               const float* __restrict__ wgt,
                                               const float* __restrict__ bia)
{
    constexpr int SLOTW = 128 * 4 + 16 * 4;  // 576 words per slot
    __shared__ float r1[20 * SLOTW];         // 46 KB
    const int tid = threadIdx.x, lane = tid & 31, warp = tid >> 5;
    const int col0 = blockIdx.x * 4;         // 4 consecutive w, same n
    const int n = col0 / Ww, w0 = col0 % Ww;
    float wk[9];
#pragma unroll
    for (int k = 0; k < 9; k++) wk[k] = wgt[k];
    const float b = bia[0];

    const float* xb = x + ((size_t)n * Cc + tid) * (Hh * Ww) + w0;   // + h*Ww
    float* ob_p = G_BUF + (size_t)n * HWC + (size_t)(w0 + warp) * Cc + lane * 4;

    const int dstw = tid * 4 + (tid >> 3) * 4;  // 16B chunk, 16B gap per 8 rows
#pragma unroll
    for (int g = 0; g < 4; g++) {            // prime h = 0..15
#pragma unroll
        for (int i = 0; i < 4; i++)
            __pipeline_memcpy_async(r1 + (g * 4 + i) * SLOTW + dstw,
                                    xb + (g * 4 + i) * Ww, 16);
        __pipeline_commit();
    }

    const int cA = 4 * lane;                 // transposed read offsets
    const int rx0 = (cA + 0) * 4 + ((cA + 0) >> 3) * 4 + warp;
    const int rx1 = (cA + 1) * 4 + ((cA + 1) >> 3) * 4 + warp;
    const int rx2 = (cA + 2) * 4 + ((cA + 2) >> 3) * 4 + warp;
    const int rx3 = (cA + 3) * 4 + ((cA + 3) >> 3) * 4 + warp;

    float d0 = 0.f, d1 = 0.f, d2 = 0.f, d3 = 0.f;
    for (int obi = 0; obi < 8; obi++) {      // 8 x 20 elements
#pragma unroll
        for (int grp = 0; grp < 5; grp++) {
            __pipeline_wait_prior(3);
            __syncthreads();
#pragma unroll
            for (int i = 0; i < 4; i++) {
                const int e = grp * 4 + i;   // slot 0..19
                const int h = obi * 20 + e;
                const float* bb = r1 + e * SLOTW;
                float c0v = bb[rx0], c1v = bb[rx1], c2v = bb[rx2], c3v = bb[rx3];
                if (h == 0) { d0 = c0v; d1 = c1v; d2 = c2v; d3 = c3v; }
                else scan_step(d0, d1, d2, d3, c0v, c1v, c2v, c3v, wk, b, lane);
                *(float4*)(ob_p + h * WC) = relu4(d0, d1, d2, d3);
            }
            if (20 * obi + 4 * grp <= 140) { // issue elements +16 .. +19
#pragma unroll
                for (int i = 0; i < 4; i++) {
                    const int e2 = (grp * 4 + 16 + i) % 20;
                    __pipeline_memcpy_async(r1 + e2 * SLOTW + dstw,
                                            xb + (20 * obi + 4 * grp + 16 + i) * Ww, 16);
                }
            }
            __pipeline_commit();
        }
    }
}

// Pass 2 (up, H descending) — in place, stride -WC.
__global__ void __launch_bounds__(128) k_pass2(const float* __restrict__ wgt,
                                               const float* __restrict__ bia)
{
    __shared__ float ring[4][16 * 128];      // 32 KB
    const int lane = threadIdx.x & 31, warp = threadIdx.x >> 5;
    const int col = blockIdx.x * 4 + warp;   // n*W + w
    const int n = col / Ww, w = col % Ww;
    float wk[9];
#pragma unroll
    for (int k = 0; k < 9; k++) wk[k] = wgt[k];
    const float b = bia[0];
    float* base = G_BUF + (size_t)n * HWC + (Hh - 1) * WC + w * Cc + (lane & 31) * 4;
    scan_col_g4<-WC>(base, ring[warp], wk, b, lane);
}

// Pass 3 (left, W ascending) — in place, stride +Cc.
__global__ void __launch_bounds__(128) k_pass3(const float* __restrict__ wgt,
                                               const float* __restrict__ bia)
{
    __shared__ float ring[4][16 * 128];
    const int lane = threadIdx.x & 31, warp = threadIdx.x >> 5;
    const int col = blockIdx.x * 4 + warp;   // n*H + h
    const int n = col / Hh, h = col % Hh;
    float wk[9];
#pragma unroll
    for (int k = 0; k < 9; k++) wk[k] = wgt[k];
    const float b = bia[0];
    float* base = G_BUF + (size_t)n * HWC + h * WC + lane * 4;
    scan_col_g4<Cc>(base, ring[warp], wk, b, lane);
}

// Pass 4 (right, W descending): G_BUF NHWC -> d_out NCHW, both spatial axes
// flipped (reference never un-flips). Same grouped ring; warp-private
// XOR-swizzled 16-step stage; flush writes 8 full 64B lines per STG round.
__global__ void __launch_bounds__(128) k_pass4(const float* __restrict__ wgt,
                                               const float* __restrict__ bia,
                                               float* __restrict__ out)
{
    __shared__ float ring[4][16 * 128];      // 32 KB
    __shared__ float stage[4][16 * 128];     // 32 KB (swizzled)
    const int lane = threadIdx.x & 31, warp = threadIdx.x >> 5;
    const int col = blockIdx.x * 4 + warp;   // n*H + h
    const int n = col / Hh, h = col % Hh;
    float wk[9];
#pragma unroll
    for (int k = 0; k < 9; k++) wk[k] = wgt[k];
    const float b = bia[0];
    const int c0 = lane * 4;

    float* p = G_BUF + (size_t)n * HWC + h * WC + (Ww - 1) * Cc + c0; // elem s at p - s*Cc
    constexpr int STRIDE = -Cc;
    float* stg = stage[warp];
    const int tq = lane & 3, cq = lane >> 2;
    const int hrow = Hh - 1 - h;
    float* const obase = out + ((size_t)n * Cc * Hh + hrow) * Ww;

    // s = 0
    float4 v0 = ld4(p);
    float d0 = v0.x, d1 = v0.y, d2 = v0.z, d3 = v0.w;
    {   // stage row 0
        const int pc = c0;                   // row 0 swizzle = identity
        *(float4*)(stg + pc) = relu4(d0, d1, d2, d3);
    }

    float* my = ring[warp] + lane * 4;
#pragma unroll
    for (int g = 0; g < 4; g++) {            // prime s = 1..16
#pragma unroll
        for (int i = 0; i < 4; i++)
            __pipeline_memcpy_async(my + (g * 4 + i) * 128,
                                    p + (1 + g * 4 + i) * STRIDE, 16);
        __pipeline_commit();
    }

#define P4_FLUSH(S0)                                                        \
    do {                                                                    \
        __syncwarp();                                                       \
        _Pragma("unroll")                                                   \
        for (int cb = 0; cb < 16; cb++) {                                   \
            const int c = cb * 8 + cq;                                      \
            const int pcf = c ^ (8 * tq);                                   \
            float4 val = make_float4(stg[(4 * tq + 0) * 128 + pcf],         \
                                     stg[(4 * tq + 1) * 128 + pcf],         \
                                     stg[(4 * tq + 2) * 128 + pcf],         \
                                     stg[(4 * tq + 3) * 128 + pcf]);        \
            __stcs((float4*)(obase + (size_t)c * (Hh * Ww) + (S0) + 4 * tq), val); \
        }                                                                   \
        __syncwarp();                                                       \
    } while (0)

    const float* rs = p + 17 * STRIDE;
    for (int obi = 0; obi < 10; obi++) {
#pragma unroll
        for (int grp = 0; grp < 4; grp++) {
            __pipeline_wait_prior(3);
#pragma unroll
            for (int i = 0; i < 4; i++) {
                const int j = grp * 4 + i;   // s = 1 + 16*obi + j; row = (j+1)&15
                float4 cx = *(float4*)(my + j * 128);
                scan_step(d0, d1, d2, d3, cx.x, cx.y, cx.z, cx.w, wk, b, lane);
                const int row = (j + 1) & 15;
                const int pc = c0 ^ (8 * ((row >> 2) & 3));
                *(float4*)(stg + row * 128 + pc) = relu4(d0, d1, d2, d3);
                if (j == 14) P4_FLUSH(16 * obi);
            }
            if (obi != 9) {
#pragma unroll
                for (int i = 0; i < 4; i++) {
                    const int j = grp * 4 + i;
                    __pipeline_memcpy_async(my + j * 128, rs + j * STRIDE, 16);
                }
            }
            __pipeline_commit();
        }
        rs += 16 * STRIDE;
    }
#undef P4_FLUSH
}

extern "C" void kernel_launch(void* const* d_in, const int* in_sizes, int n_in,
                              void* d_out, int out_size)
{
    (void)in_sizes; (void)n_in; (void)out_size;
    const float* x  = (const float*)d_in[0];
    const float* wd = (const float*)d_in[1];
    const float* bd = (const float*)d_in[2];
    const float* wu = (const float*)d_in[3];
    const float* bu = (const float*)d_in[4];
    const float* wl = (const float*)d_in[5];
    const float* bl = (const float*)d_in[6];
    const float* wr = (const float*)d_in[7];
    const float* br = (const float*)d_in[8];
    float* out = (float*)d_out;

    k_pass1<<<320, 128>>>(x, wd, bd);
    k_pass2<<<320, 128>>>(wu, bu);
    k_pass3<<<320, 128>>>(wl, bl);
    k_pass4<<<320, 128>>>(wr, br, out);
}

// round 9
// speedup vs baseline: 1.5704x; 1.5704x over previous
#include <cuda_runtime.h>
#include <cuda_pipeline.h>

#define FULLMASK 0xffffffffu

constexpr int Nn = 8;
constexpr int Cc = 128;
constexpr int Hh = 160;
constexpr int Ww = 160;
constexpr int HWC = Hh * Ww * Cc;        // per-image NHWC stride
constexpr int TOT = Nn * HWC;

// Single in-place NHWC scratch buffer.
__device__ float g_buf[TOT];

__device__ __forceinline__ float4 ld4(const float* p)  { return *(const float4*)p; }

__device__ __forceinline__ float4 relu4(float a, float b, float c, float d) {
    return make_float4(fmaxf(a, 0.f), fmaxf(b, 0.f), fmaxf(c, 0.f), fmaxf(d, 0.f));
}

// One scan step: carry d0..d3 (pre-relu state, 4 consecutive channels/lane),
// 9-tap conv along C via lane shuffles, zero-padded at C boundaries.
// d_new = relu(conv(d) + b) + x. Split accumulators shorten the FMA chain.
__device__ __forceinline__ void scan_step(float& d0, float& d1, float& d2, float& d3,
                                          float x0, float x1, float x2, float x3,
                                          const float wk[9], float b, int lane)
{
    float v[12];
    v[4] = d0; v[5] = d1; v[6] = d2; v[7] = d3;
    v[0]  = __shfl_up_sync(FULLMASK, d0, 1);
    v[1]  = __shfl_up_sync(FULLMASK, d1, 1);
    v[2]  = __shfl_up_sync(FULLMASK, d2, 1);
    v[3]  = __shfl_up_sync(FULLMASK, d3, 1);
    v[8]  = __shfl_down_sync(FULLMASK, d0, 1);
    v[9]  = __shfl_down_sync(FULLMASK, d1, 1);
    v[10] = __shfl_down_sync(FULLMASK, d2, 1);
    v[11] = __shfl_down_sync(FULLMASK, d3, 1);
    if (lane == 0)  { v[0] = 0.f; v[1] = 0.f; v[2]  = 0.f; v[3]  = 0.f; }
    if (lane == 31) { v[8] = 0.f; v[9] = 0.f; v[10] = 0.f; v[11] = 0.f; }
    float a0 = b, a1 = b, a2 = b, a3 = b;
    float e0 = 0.f, e1 = 0.f, e2 = 0.f, e3 = 0.f;
#pragma unroll
    for (int k = 0; k < 5; k++) {
        a0 = fmaf(wk[k], v[k + 0], a0);
        a1 = fmaf(wk[k], v[k + 1], a1);
        a2 = fmaf(wk[k], v[k + 2], a2);
        a3 = fmaf(wk[k], v[k + 3], a3);
    }
#pragma unroll
    for (int k = 5; k < 9; k++) {
        e0 = fmaf(wk[k], v[k + 0], e0);
        e1 = fmaf(wk[k], v[k + 1], e1);
        e2 = fmaf(wk[k], v[k + 2], e2);
        e3 = fmaf(wk[k], v[k + 3], e3);
    }
    d0 = fmaxf(a0 + e0, 0.f) + x0;
    d1 = fmaxf(a1 + e1, 0.f) + x1;
    d2 = fmaxf(a2 + e2, 0.f) + x2;
    d3 = fmaxf(a3 + e3, 0.f) + x3;
}

// In-place NHWC column scan, cp.async ring depth 16, pair-unrolled.
// ring: per-warp smem, 16 slots x 512 B. p -> element 0 (+c0); stride signed.
__device__ __forceinline__ void scan_col_ring16(float* __restrict__ p, int stride,
                                                float* __restrict__ ring,
                                                const float wk[9], float b, int lane)
{
    float4 v0 = ld4(p);
    float d0 = v0.x, d1 = v0.y, d2 = v0.z, d3 = v0.w;
    *(float4*)p = relu4(d0, d1, d2, d3);

    float* my = ring + lane * 4;   // slot s at my + s*128
#pragma unroll
    for (int i = 0; i < 16; i++) {
        __pipeline_memcpy_async(my + i * 128, p + (1 + i) * stride, 16);
        __pipeline_commit();
    }
    for (int t = 1; t + 1 < 160; t += 2) {
        __pipeline_wait_prior(14);               // elements t, t+1 complete
        float* sl0 = my + ((t - 1) & 15) * 128;
        float* sl1 = my + (t & 15) * 128;
        float4 cx0 = *(float4*)sl0;
        float4 cx1 = *(float4*)sl1;
        if (t + 16 < 160) __pipeline_memcpy_async(sl0, p + (t + 16) * stride, 16);
        __pipeline_commit();
        if (t + 17 < 160) __pipeline_memcpy_async(sl1, p + (t + 17) * stride, 16);
        __pipeline_commit();
        scan_step(d0, d1, d2, d3, cx0.x, cx0.y, cx0.z, cx0.w, wk, b, lane);
        *(float4*)(p + t * stride) = relu4(d0, d1, d2, d3);
        scan_step(d0, d1, d2, d3, cx1.x, cx1.y, cx1.z, cx1.w, wk, b, lane);
        *(float4*)(p + (t + 1) * stride) = relu4(d0, d1, d2, d3);
    }
    // t = 159
    __pipeline_wait_prior(0);
    float4 cx = *(float4*)(my + ((159 - 1) & 15) * 128);
    scan_step(d0, d1, d2, d3, cx.x, cx.y, cx.z, cx.w, wk, b, lane);
    *(float4*)(p + 159 * stride) = relu4(d0, d1, d2, d3);
}

// Pass 1 (down, H ascending): x NCHW -> g_buf NHWC. cp.async staging ring
// (18 slots, depth 16), transpose on the smem read side, one __syncthreads
// per 2 elements. (128-thread cooperative block — unchanged from R6.)
__global__ void __launch_bounds__(128) k_pass1(const float* __restrict__ x,
                                               const float* __restrict__ wgt,
                                               const float* __restrict__ bia)
{
    constexpr int SLOTS = 18, DEPTH = 16, SLOTW = 128 * 4 + 16 * 4;  // 576 words
    __shared__ float r1[SLOTS * SLOTW];          // ~41.5 KB
    const int tid = threadIdx.x, lane = tid & 31, warp = tid >> 5;
    const int col0 = blockIdx.x * 4;             // 4 consecutive w, same n
    const int n = col0 / Ww, w0 = col0 % Ww;
    float wk[9];
#pragma unroll
    for (int k = 0; k < 9; k++) wk[k] = wgt[k];
    const float b = bia[0];

    const float* xb = x + ((size_t)n * Cc + tid) * (Hh * Ww) + w0;   // + h*Ww
    float* ob = g_buf + (size_t)n * HWC + (size_t)(w0 + warp) * Cc + lane * 4;

    const int dstw = tid * 4 + (tid >> 3) * 4;   // 16B chunk, 16B gap per 8 rows
#pragma unroll
    for (int i = 0; i < DEPTH; i++) {
        __pipeline_memcpy_async(r1 + i * SLOTW + dstw, xb + i * Ww, 16);
        __pipeline_commit();
    }

    // transposed read offsets: channels 4*lane..+3 of column `warp`
    const int cA = 4 * lane;
    const int rx0 = (cA + 0) * 4 + ((cA + 0) >> 3) * 4 + warp;
    const int rx1 = (cA + 1) * 4 + ((cA + 1) >> 3) * 4 + warp;
    const int rx2 = (cA + 2) * 4 + ((cA + 2) >> 3) * 4 + warp;
    const int rx3 = (cA + 3) * 4 + ((cA + 3) >> 3) * 4 + warp;

    float d0 = 0.f, d1 = 0.f, d2 = 0.f, d3 = 0.f;
    int sl_r = 0, sl_w = DEPTH;
    for (int h = 0; h < 160; h += 2) {
        __pipeline_wait_prior(DEPTH - 2);        // this thread's h, h+1 landed
        __syncthreads();                         // all threads' copies visible
        int sr1 = sl_r + 1; if (sr1 == SLOTS) sr1 = 0;
        const float* b0 = r1 + sl_r * SLOTW;
        const float* b1 = r1 + sr1 * SLOTW;
        float c00 = b0[rx0], c01 = b0[rx1], c02 = b0[rx2], c03 = b0[rx3];
        float c10 = b1[rx0], c11 = b1[rx1], c12 = b1[rx2], c13 = b1[rx3];
        int sw1 = sl_w + 1; if (sw1 == SLOTS) sw1 = 0;
        if (h + DEPTH < Hh)
            __pipeline_memcpy_async(r1 + sl_w * SLOTW + dstw, xb + (h + DEPTH) * Ww, 16);
        __pipeline_commit();
        if (h + DEPTH + 1 < Hh)
            __pipeline_memcpy_async(r1 + sw1 * SLOTW + dstw, xb + (h + DEPTH + 1) * Ww, 16);
        __pipeline_commit();

        if (h == 0) { d0 = c00; d1 = c01; d2 = c02; d3 = c03; }
        else scan_step(d0, d1, d2, d3, c00, c01, c02, c03, wk, b, lane);
        *(float4*)(ob + h * (Ww * Cc)) = relu4(d0, d1, d2, d3);
        scan_step(d0, d1, d2, d3, c10, c11, c12, c13, wk, b, lane);
        *(float4*)(ob + (h + 1) * (Ww * Cc)) = relu4(d0, d1, d2, d3);

        sl_r += 2; if (sl_r >= SLOTS) sl_r -= SLOTS;
        sl_w += 2; if (sl_w >= SLOTS) sl_w -= SLOTS;
    }
}

// Pass 2 (up, H descending) — in place. ONE warp per block (grid 1280) for
// near-perfect SM load balance (9 vs 8 blocks/SM instead of 3 vs 2).
__global__ void __launch_bounds__(32) k_pass2(const float* __restrict__ wgt,
                                              const float* __restrict__ bia)
{
    __shared__ float ring[16 * 128];             // 8 KB
    const int lane = threadIdx.x & 31;
    const int col = blockIdx.x;                  // n*W + w
    const int n = col / Ww, w = col % Ww;
    float wk[9];
#pragma unroll
    for (int k = 0; k < 9; k++) wk[k] = wgt[k];
    const float b = bia[0];
    const int base = n * HWC + (Hh - 1) * (Ww * Cc) + w * Cc + lane * 4;  // h = H-1
    scan_col_ring16(g_buf + base, -(Ww * Cc), ring, wk, b, lane);
}

// Pass 3 (left, W ascending) — in place. One warp per block.
__global__ void __launch_bounds__(32) k_pass3(const float* __restrict__ wgt,
                                              const float* __restrict__ bia)
{
    __shared__ float ring[16 * 128];
    const int lane = threadIdx.x & 31;
    const int col = blockIdx.x;                  // n*H + h
    const int n = col / Hh, h = col % Hh;
    float wk[9];
#pragma unroll
    for (int k = 0; k < 9; k++) wk[k] = wgt[k];
    const float b = bia[0];
    const int base = n * HWC + h * (Ww * Cc) + lane * 4;                  // w = 0
    scan_col_ring16(g_buf + base, Cc, ring, wk, b, lane);
}

// Pass 4 (right, W descending): g_buf NHWC -> d_out NCHW, both spatial axes
// flipped (reference never un-flips). Depth-16 ring; warp-private 16-step
// XOR-swizzled stage; flush writes 8 full 64B lines per STG round.
// One warp per block.
__device__ __forceinline__ void p4_stage_write(float* stg, int row, int c0,
                                               float4 val)
{
    const int pc = c0 ^ (8 * ((row >> 2) & 3));
    *(float4*)(stg + row * 128 + pc) = val;
}

__global__ void __launch_bounds__(32) k_pass4(const float* __restrict__ wgt,
                                              const float* __restrict__ bia,
                                              float* __restrict__ out)
{
    __shared__ float ring[16 * 128];             // 8 KB
    __shared__ float stage[16 * 128];            // 8 KB (swizzled)
    const int lane = threadIdx.x & 31;
    const int col = blockIdx.x;                  // n*H + h
    const int n = col / Hh, h = col % Hh;
    float wk[9];
#pragma unroll
    for (int k = 0; k < 9; k++) wk[k] = wgt[k];
    const float b = bia[0];
    const int c0 = lane * 4;

    const float* inp = g_buf + n * HWC + h * (Ww * Cc) + c0;  // + w*Cc
    float* stg = stage;
    const int tq = lane & 3, cq = lane >> 2;
    const int hrow = Hh - 1 - h;                 // flipped output h
    float* const obase = out + ((size_t)n * Cc * Hh + hrow) * Ww;

    // s = 0 <-> w = W-1
    float4 v0 = ld4(inp + (Ww - 1) * Cc);
    float d0 = v0.x, d1 = v0.y, d2 = v0.z, d3 = v0.w;
    p4_stage_write(stg, 0, c0, relu4(d0, d1, d2, d3));

    float* my = ring + lane * 4;
#pragma unroll
    for (int i = 0; i < 16; i++) {               // element s = 1+i
        __pipeline_memcpy_async(my + i * 128, inp + (Ww - 2 - i) * Cc, 16);
        __pipeline_commit();
    }

#define P4_FLUSH(S0)                                                        \
    do {                                                                    \
        __syncwarp();                                                       \
        _Pragma("unroll")                                                   \
        for (int cb = 0; cb < 16; cb++) {                                   \
            const int c = cb * 8 + cq;                                      \
            const int pcf = c ^ (8 * tq);                                   \
            float4 val = make_float4(stg[(4 * tq + 0) * 128 + pcf],         \
                                     stg[(4 * tq + 1) * 128 + pcf],         \
                                     stg[(4 * tq + 2) * 128 + pcf],         \
                                     stg[(4 * tq + 3) * 128 + pcf]);        \
            __stcs((float4*)(obase + (size_t)c * (Hh * Ww) + (S0) + 4 * tq), val); \
        }                                                                   \
        __syncwarp();                                                       \
    } while (0)

    for (int s = 1; s + 1 < 160; s += 2) {
        __pipeline_wait_prior(14);
        float* sl0 = my + ((s - 1) & 15) * 128;
        float* sl1 = my + (s & 15) * 128;
        float4 cx0 = *(float4*)sl0;
        float4 cx1 = *(float4*)sl1;
        if (s + 16 < 160) __pipeline_memcpy_async(sl0, inp + (Ww - 1 - (s + 16)) * Cc, 16);
        __pipeline_commit();
        if (s + 17 < 160) __pipeline_memcpy_async(sl1, inp + (Ww - 1 - (s + 17)) * Cc, 16);
        __pipeline_commit();

        scan_step(d0, d1, d2, d3, cx0.x, cx0.y, cx0.z, cx0.w, wk, b, lane);
        p4_stage_write(stg, s & 15, c0, relu4(d0, d1, d2, d3));
        if ((s & 15) == 15) P4_FLUSH(s - 15);

        scan_step(d0, d1, d2, d3, cx1.x, cx1.y, cx1.z, cx1.w, wk, b, lane);
        p4_stage_write(stg, (s + 1) & 15, c0, relu4(d0, d1, d2, d3));
        if (((s + 1) & 15) == 15) P4_FLUSH(s - 14);
    }
    // s = 159
    __pipeline_wait_prior(0);
    {
        float4 cx = *(float4*)(my + ((159 - 1) & 15) * 128);
        scan_step(d0, d1, d2, d3, cx.x, cx.y, cx.z, cx.w, wk, b, lane);
        p4_stage_write(stg, 15, c0, relu4(d0, d1, d2, d3));
        P4_FLUSH(144);
    }
#undef P4_FLUSH
}

extern "C" void kernel_launch(void* const* d_in, const int* in_sizes, int n_in,
                              void* d_out, int out_size)
{
    (void)in_sizes; (void)n_in; (void)out_size;
    const float* x  = (const float*)d_in[0];
    const float* wd = (const float*)d_in[1];
    const float* bd = (const float*)d_in[2];
    const float* wu = (const float*)d_in[3];
    const float* bu = (const float*)d_in[4];
    const float* wl = (const float*)d_in[5];
    const float* bl = (const float*)d_in[6];
    const float* wr = (const float*)d_in[7];
    const float* br = (const float*)d_in[8];
    float* out = (float*)d_out;

    k_pass1<<<320, 128>>>(x, wd, bd);
    k_pass2<<<1280, 32>>>(wu, bu);
    k_pass3<<<1280, 32>>>(wl, bl);
    k_pass4<<<1280, 32>>>(wr, br, out);
}